// round 11
// baseline (speedup 1.0000x reference)
#include <cuda_runtime.h>

// Problem dims (fixed by reference)
#define B 16
#define S 4096
#define D 1024      // D_IN = H = D_OUT = 1024
#define NCHUNK 64
#define SCHUNK (S / NCHUNK)   // 64
#define KSPLIT 8
#define KCHUNK (D / KSPLIT)   // 128
#define R_GRID 512            // K1 blocks; each handles 2 of the 1024 tasks

// Scratch (no device allocs allowed)
__device__ float g_m[B * D];
__device__ float g_enc[B * D];

// ---------------------------------------------------------------------------
// K0: zero the mean accumulator, pre-init enc/out with biases.
__global__ void init_kernel(float* __restrict__ m,
                            const float* __restrict__ b_enc,
                            float* __restrict__ enc,
                            const float* __restrict__ b_out,
                            float* __restrict__ out) {
    const int i = blockIdx.x * blockDim.x + threadIdx.x;  // 0 .. B*D-1
    const int d = i & (D - 1);
    m[i]   = 0.f;
    enc[i] = b_enc[d];
    out[i] = b_out[d];
}

// ---------------------------------------------------------------------------
// K1: partial sums over S-chunks, scaled by 1/S, atomicAdd'ed straight into m
// (replaces the part buffer + combine kernel). grid R_GRID, block 256,
// 2 tasks per block. 8 LDG.128 batched per iteration for DRAM-latency MLP.
// PDL: the first task's entire x-load/accumulate phase runs BEFORE the
// dependency sync, hiding K0 completely; atomics commit after the sync.
__global__ void reduce_kernel(const float* __restrict__ x,
                              float* __restrict__ m) {
    const int tid = threadIdx.x;  // 0..255
    float4 task_acc[2];

    #pragma unroll
    for (int t = 0; t < 2; t++) {
        const int task = blockIdx.x + t * R_GRID;   // 0..1023
        const int b = task >> 6;                    // task / NCHUNK
        const int chunk = task & (NCHUNK - 1);

        const float4* xb = (const float4*)(x + (size_t)b * S * D
                                             + (size_t)chunk * SCHUNK * D);

        float4 acc0 = make_float4(0.f, 0.f, 0.f, 0.f);
        float4 acc1 = make_float4(0.f, 0.f, 0.f, 0.f);
        float4 acc2 = make_float4(0.f, 0.f, 0.f, 0.f);
        float4 acc3 = make_float4(0.f, 0.f, 0.f, 0.f);

        #pragma unroll 2
        for (int s = 0; s < SCHUNK; s += 8) {
            float4 v[8];
            #pragma unroll
            for (int j = 0; j < 8; j++)
                v[j] = __ldcs(&xb[(size_t)(s + j) * (D / 4) + tid]);
            #pragma unroll
            for (int j = 0; j < 8; j += 4) {
                acc0.x += v[j].x;   acc0.y += v[j].y;   acc0.z += v[j].z;   acc0.w += v[j].w;
                acc1.x += v[j+1].x; acc1.y += v[j+1].y; acc1.z += v[j+1].z; acc1.w += v[j+1].w;
                acc2.x += v[j+2].x; acc2.y += v[j+2].y; acc2.z += v[j+2].z; acc2.w += v[j+2].w;
                acc3.x += v[j+3].x; acc3.y += v[j+3].y; acc3.z += v[j+3].z; acc3.w += v[j+3].w;
            }
        }

        float4 a;
        const float inv = 1.0f / (float)S;
        a.x = ((acc0.x + acc1.x) + (acc2.x + acc3.x)) * inv;
        a.y = ((acc0.y + acc1.y) + (acc2.y + acc3.y)) * inv;
        a.z = ((acc0.z + acc1.z) + (acc2.z + acc3.z)) * inv;
        a.w = ((acc0.w + acc1.w) + (acc2.w + acc3.w)) * inv;
        task_acc[t] = a;

        if (t == 0)
            cudaGridDependencySynchronize();   // m zeroed by K0; commit is safe

        float* md = m + (size_t)b * D + tid * 4;
        atomicAdd(md + 0, a.x);
        atomicAdd(md + 1, a.y);
        atomicAdd(md + 2, a.z);
        atomicAdd(md + 3, a.w);
    }
    (void)task_acc;
}

// ---------------------------------------------------------------------------
// K2/K3: split-K batched GEMV with smem-staged activations.
// PDL: the W row LDG (pure input) issues while the predecessor kernel is
// still running; everything touching vin/vout waits at the dependency sync.
__global__ void __launch_bounds__(256)
gemv_split_kernel(const float* __restrict__ vin,   // [B, D]
                  const float* __restrict__ W,     // [D, D]
                  float* __restrict__ vout) {      // [B, D] (+=)
    __shared__ float4 sh[B * (KCHUNK / 4)];   // 16 x 32 float4 = 8 KB

    const int K0 = blockIdx.y * KCHUNK;
    const int warp = threadIdx.x >> 5;
    const int lane = threadIdx.x & 31;
    const int n = blockIdx.x * 8 + warp;

    // Prologue: W row load overlaps the predecessor's tail + our ramp.
    const float4 w = __ldg(&((const float4*)(W + (size_t)n * D + K0))[lane]);

    cudaGridDependencySynchronize();   // vin/vout now valid

    // Cooperative fill: vin[:, K0:K0+128] -> 8 KB smem.
    {
        const float4* v4 = (const float4*)vin;
        sh[warp * 32 + lane]       = v4[(size_t)warp * (D / 4)       + K0 / 4 + lane];
        sh[(warp + 8) * 32 + lane] = v4[(size_t)(warp + 8) * (D / 4) + K0 / 4 + lane];
    }
    __syncthreads();

    float acc[B];
    #pragma unroll
    for (int b = 0; b < B; b++) {
        float4 v = sh[b * 32 + lane];
        acc[b] = ((w.x * v.x + w.y * v.y) + (w.z * v.z + w.w * v.w));
    }

    // Interleaved pairwise reduction: 16 SHFLs; lane l ends with b = l & 15.
    float u8[8];
    #pragma unroll
    for (int j = 0; j < 8; j++) {
        float mine  = (lane & 1) ? acc[2 * j + 1] : acc[2 * j];
        float other = (lane & 1) ? acc[2 * j]     : acc[2 * j + 1];
        u8[j] = mine + __shfl_xor_sync(0xFFFFFFFFu, other, 1);
    }
    float u4[4];
    #pragma unroll
    for (int j = 0; j < 4; j++) {
        float mine  = (lane & 2) ? u8[2 * j + 1] : u8[2 * j];
        float other = (lane & 2) ? u8[2 * j]     : u8[2 * j + 1];
        u4[j] = mine + __shfl_xor_sync(0xFFFFFFFFu, other, 2);
    }
    float u2[2];
    #pragma unroll
    for (int j = 0; j < 2; j++) {
        float mine  = (lane & 4) ? u4[2 * j + 1] : u4[2 * j];
        float other = (lane & 4) ? u4[2 * j]     : u4[2 * j + 1];
        u2[j] = mine + __shfl_xor_sync(0xFFFFFFFFu, other, 4);
    }
    float mine  = (lane & 8) ? u2[1] : u2[0];
    float other = (lane & 8) ? u2[0] : u2[1];
    float u = mine + __shfl_xor_sync(0xFFFFFFFFu, other, 8);
    u += __shfl_xor_sync(0xFFFFFFFFu, u, 16);

    if (lane < B)
        atomicAdd(&vout[(size_t)lane * D + n], u);
}

// ---------------------------------------------------------------------------
extern "C" void kernel_launch(void* const* d_in, const int* in_sizes, int n_in,
                              void* d_out, int out_size) {
    const float* x     = (const float*)d_in[0];
    const float* W_enc = (const float*)d_in[1];
    const float* b_enc = (const float*)d_in[2];
    const float* W_out = (const float*)d_in[3];
    const float* b_out = (const float*)d_in[4];
    float* out = (float*)d_out;

    float* m;    cudaGetSymbolAddress((void**)&m,    g_m);
    float* enc;  cudaGetSymbolAddress((void**)&enc,  g_enc);

    cudaLaunchAttribute attr[1];
    attr[0].id = cudaLaunchAttributeProgrammaticStreamSerialization;
    attr[0].val.programmaticStreamSerializationAllowed = 1;

    // K0: init (normal launch, first in stream).
    init_kernel<<<(B * D) / 256, 256>>>(m, b_enc, enc, b_out, out);

    // K1: reduction with PDL — x-load phase overlaps K0 entirely.
    {
        cudaLaunchConfig_t cfg = {};
        cfg.gridDim = dim3(R_GRID);
        cfg.blockDim = dim3(256);
        cfg.stream = 0;
        cfg.attrs = attr;
        cfg.numAttrs = 1;
        cudaLaunchKernelEx(&cfg, reduce_kernel, x, m);
    }
    // K2/K3: GEMVs with PDL — W prefetch overlaps predecessor tail.
    {
        cudaLaunchConfig_t cfg = {};
        cfg.gridDim = dim3(D / 8, KSPLIT);
        cfg.blockDim = dim3(256);
        cfg.stream = 0;
        cfg.attrs = attr;
        cfg.numAttrs = 1;
        cudaLaunchKernelEx(&cfg, gemv_split_kernel,
                           (const float*)m, W_enc, enc);
    }
    {
        cudaLaunchConfig_t cfg = {};
        cfg.gridDim = dim3(D / 8, KSPLIT);
        cfg.blockDim = dim3(256);
        cfg.stream = 0;
        cfg.attrs = attr;
        cfg.numAttrs = 1;
        cudaLaunchKernelEx(&cfg, gemv_split_kernel,
                           (const float*)enc, W_out, out);
    }
}

// round 12
// speedup vs baseline: 1.0236x; 1.0236x over previous
#include <cuda_runtime.h>

// Problem dims (fixed by reference)
#define B 16
#define S 4096
#define D 1024      // D_IN = H = D_OUT = 1024
#define NCHUNK 32
#define SCHUNK (S / NCHUNK)   // 128
#define KSPLIT 8
#define KCHUNK (D / KSPLIT)   // 128
#define R_GRID (B * NCHUNK)   // 512 K1 blocks, one contiguous chunk each

// Scratch (no device allocs allowed)
__device__ float g_part[B * NCHUNK * D];   // 2 MB
__device__ float g_m[B * D];
__device__ float g_enc[B * D];

// ---------------------------------------------------------------------------
// K1: partial sums over one contiguous 128-row S-chunk per block.
// grid R_GRID, block 256. 8 LDG.128 batched per iteration for DRAM MLP.
// Streaming loads (__ldcs): x is read-once, keep it out of L2.
__global__ void reduce_partial_kernel(const float* __restrict__ x,
                                      float* __restrict__ part) {
    const int tid = threadIdx.x;                // 0..255
    const int b = blockIdx.x >> 5;              // / NCHUNK
    const int chunk = blockIdx.x & (NCHUNK - 1);

    const float4* xb = (const float4*)(x + (size_t)b * S * D
                                         + (size_t)chunk * SCHUNK * D);

    float4 acc0 = make_float4(0.f, 0.f, 0.f, 0.f);
    float4 acc1 = make_float4(0.f, 0.f, 0.f, 0.f);
    float4 acc2 = make_float4(0.f, 0.f, 0.f, 0.f);
    float4 acc3 = make_float4(0.f, 0.f, 0.f, 0.f);

    #pragma unroll 2
    for (int s = 0; s < SCHUNK; s += 8) {
        float4 v[8];
        #pragma unroll
        for (int j = 0; j < 8; j++)
            v[j] = __ldcs(&xb[(size_t)(s + j) * (D / 4) + tid]);
        #pragma unroll
        for (int j = 0; j < 8; j += 4) {
            acc0.x += v[j].x;   acc0.y += v[j].y;   acc0.z += v[j].z;   acc0.w += v[j].w;
            acc1.x += v[j+1].x; acc1.y += v[j+1].y; acc1.z += v[j+1].z; acc1.w += v[j+1].w;
            acc2.x += v[j+2].x; acc2.y += v[j+2].y; acc2.z += v[j+2].z; acc2.w += v[j+2].w;
            acc3.x += v[j+3].x; acc3.y += v[j+3].y; acc3.z += v[j+3].z; acc3.w += v[j+3].w;
        }
    }

    float4 acc;
    acc.x = (acc0.x + acc1.x) + (acc2.x + acc3.x);
    acc.y = (acc0.y + acc1.y) + (acc2.y + acc3.y);
    acc.z = (acc0.z + acc1.z) + (acc2.z + acc3.z);
    acc.w = (acc0.w + acc1.w) + (acc2.w + acc3.w);

    float4* p = (float4*)(part + ((size_t)b * NCHUNK + chunk) * D);
    p[tid] = acc;

    // Let the combine grid launch as early as legal.
    cudaTriggerProgrammaticLaunchCompletion();
}

// ---------------------------------------------------------------------------
// K2: combine partials -> mean, pre-init enc/out with biases.
// grid 128 x 128 threads. PDL: bias prologue overlaps K1's tail.
__global__ void combine_kernel(const float* __restrict__ part,
                               float* __restrict__ m,
                               const float* __restrict__ b_enc,
                               float* __restrict__ enc,
                               const float* __restrict__ b_out,
                               float* __restrict__ out) {
    const int i = blockIdx.x * blockDim.x + threadIdx.x;  // 0 .. B*D-1
    const int d = i & (D - 1);

    const float be = b_enc[d];
    const float bo = b_out[d];

    cudaGridDependencySynchronize();   // wait for K1's partials

    const int b = i >> 10;
    float s = 0.f;
    #pragma unroll
    for (int c = 0; c < NCHUNK; c++)
        s += part[((size_t)b * NCHUNK + c) * D + d];
    m[i] = s * (1.0f / (float)S);
    enc[i] = be;
    out[i] = bo;

    cudaTriggerProgrammaticLaunchCompletion();
}

// ---------------------------------------------------------------------------
// K3/K4: split-K batched GEMV with smem-staged activations.
// PDL: the W row LDG (pure input) issues while the predecessor kernel is
// still running; everything touching vin/vout waits at the dependency sync.
__global__ void __launch_bounds__(256)
gemv_split_kernel(const float* __restrict__ vin,   // [B, D]
                  const float* __restrict__ W,     // [D, D]
                  float* __restrict__ vout) {      // [B, D] (+=)
    __shared__ float4 sh[B * (KCHUNK / 4)];   // 16 x 32 float4 = 8 KB

    const int K0 = blockIdx.y * KCHUNK;
    const int warp = threadIdx.x >> 5;
    const int lane = threadIdx.x & 31;
    const int n = blockIdx.x * 8 + warp;

    // Prologue: W row load overlaps the predecessor's tail + our ramp.
    const float4 w = __ldg(&((const float4*)(W + (size_t)n * D + K0))[lane]);

    cudaGridDependencySynchronize();   // vin/vout now valid

    // Cooperative fill: vin[:, K0:K0+128] -> 8 KB smem.
    {
        const float4* v4 = (const float4*)vin;
        sh[warp * 32 + lane]       = v4[(size_t)warp * (D / 4)       + K0 / 4 + lane];
        sh[(warp + 8) * 32 + lane] = v4[(size_t)(warp + 8) * (D / 4) + K0 / 4 + lane];
    }
    __syncthreads();

    float acc[B];
    #pragma unroll
    for (int b = 0; b < B; b++) {
        float4 v = sh[b * 32 + lane];
        acc[b] = ((w.x * v.x + w.y * v.y) + (w.z * v.z + w.w * v.w));
    }

    // Interleaved pairwise reduction: 16 SHFLs; lane l ends with b = l & 15.
    float u8[8];
    #pragma unroll
    for (int j = 0; j < 8; j++) {
        float mine  = (lane & 1) ? acc[2 * j + 1] : acc[2 * j];
        float other = (lane & 1) ? acc[2 * j]     : acc[2 * j + 1];
        u8[j] = mine + __shfl_xor_sync(0xFFFFFFFFu, other, 1);
    }
    float u4[4];
    #pragma unroll
    for (int j = 0; j < 4; j++) {
        float mine  = (lane & 2) ? u8[2 * j + 1] : u8[2 * j];
        float other = (lane & 2) ? u8[2 * j]     : u8[2 * j + 1];
        u4[j] = mine + __shfl_xor_sync(0xFFFFFFFFu, other, 2);
    }
    float u2[2];
    #pragma unroll
    for (int j = 0; j < 2; j++) {
        float mine  = (lane & 4) ? u4[2 * j + 1] : u4[2 * j];
        float other = (lane & 4) ? u4[2 * j]     : u4[2 * j + 1];
        u2[j] = mine + __shfl_xor_sync(0xFFFFFFFFu, other, 4);
    }
    float mine  = (lane & 8) ? u2[1] : u2[0];
    float other = (lane & 8) ? u2[0] : u2[1];
    float u = mine + __shfl_xor_sync(0xFFFFFFFFu, other, 8);
    u += __shfl_xor_sync(0xFFFFFFFFu, u, 16);

    if (lane < B)
        atomicAdd(&vout[(size_t)lane * D + n], u);

    cudaTriggerProgrammaticLaunchCompletion();
}

// ---------------------------------------------------------------------------
extern "C" void kernel_launch(void* const* d_in, const int* in_sizes, int n_in,
                              void* d_out, int out_size) {
    const float* x     = (const float*)d_in[0];
    const float* W_enc = (const float*)d_in[1];
    const float* b_enc = (const float*)d_in[2];
    const float* W_out = (const float*)d_in[3];
    const float* b_out = (const float*)d_in[4];
    float* out = (float*)d_out;

    float* part; cudaGetSymbolAddress((void**)&part, g_part);
    float* m;    cudaGetSymbolAddress((void**)&m,    g_m);
    float* enc;  cudaGetSymbolAddress((void**)&enc,  g_enc);

    // K1: normal launch.
    reduce_partial_kernel<<<R_GRID, 256>>>(x, part);

    // Tail kernels: PDL so each overlaps the predecessor's tail/ramp.
    cudaLaunchAttribute attr[1];
    attr[0].id = cudaLaunchAttributeProgrammaticStreamSerialization;
    attr[0].val.programmaticStreamSerializationAllowed = 1;

    {
        cudaLaunchConfig_t cfg = {};
        cfg.gridDim = dim3((B * D) / 128);
        cfg.blockDim = dim3(128);
        cfg.stream = 0;
        cfg.attrs = attr;
        cfg.numAttrs = 1;
        cudaLaunchKernelEx(&cfg, combine_kernel,
                           (const float*)part, m, b_enc, enc, b_out, out);
    }
    {
        cudaLaunchConfig_t cfg = {};
        cfg.gridDim = dim3(D / 8, KSPLIT);
        cfg.blockDim = dim3(256);
        cfg.stream = 0;
        cfg.attrs = attr;
        cfg.numAttrs = 1;
        cudaLaunchKernelEx(&cfg, gemv_split_kernel,
                           (const float*)m, W_enc, enc);
    }
    {
        cudaLaunchConfig_t cfg = {};
        cfg.gridDim = dim3(D / 8, KSPLIT);
        cfg.blockDim = dim3(256);
        cfg.stream = 0;
        cfg.attrs = attr;
        cfg.numAttrs = 1;
        cudaLaunchKernelEx(&cfg, gemv_split_kernel,
                           (const float*)enc, W_out, out);
    }
}

// round 14
// speedup vs baseline: 1.0465x; 1.0224x over previous
#include <cuda_runtime.h>

// Problem dims (fixed by reference)
#define B 16
#define S 4096
#define D 1024      // D_IN = H = D_OUT = 1024
#define NCHUNK 64
#define SCHUNK (S / NCHUNK)   // 64
#define KSPLIT 4
#define KCHUNK (D / KSPLIT)   // 256
#define R_GRID 512            // K1 blocks; each handles 2 of the 1024 tasks

// Scratch (no device allocs allowed)
__device__ float g_part[B * NCHUNK * D];   // 4 MB
__device__ float g_m[B * D];
__device__ float g_enc[B * D];

// ---------------------------------------------------------------------------
// K1: partial sums over S-chunks. grid R_GRID, block 256, 2 tasks per block.
// 8 LDG.128 batched per iteration for DRAM-latency MLP; __ldcs (read-once).
__global__ void reduce_partial_kernel(const float* __restrict__ x,
                                      float* __restrict__ part) {
    const int tid = threadIdx.x;  // 0..255

    #pragma unroll
    for (int t = 0; t < 2; t++) {
        const int task = blockIdx.x + t * R_GRID;   // 0..1023
        const int b = task >> 6;                    // task / NCHUNK
        const int chunk = task & (NCHUNK - 1);

        const float4* xb = (const float4*)(x + (size_t)b * S * D
                                             + (size_t)chunk * SCHUNK * D);

        float4 acc0 = make_float4(0.f, 0.f, 0.f, 0.f);
        float4 acc1 = make_float4(0.f, 0.f, 0.f, 0.f);
        float4 acc2 = make_float4(0.f, 0.f, 0.f, 0.f);
        float4 acc3 = make_float4(0.f, 0.f, 0.f, 0.f);

        #pragma unroll 2
        for (int s = 0; s < SCHUNK; s += 8) {
            float4 v[8];
            #pragma unroll
            for (int j = 0; j < 8; j++)
                v[j] = __ldcs(&xb[(size_t)(s + j) * (D / 4) + tid]);
            #pragma unroll
            for (int j = 0; j < 8; j += 4) {
                acc0.x += v[j].x;   acc0.y += v[j].y;   acc0.z += v[j].z;   acc0.w += v[j].w;
                acc1.x += v[j+1].x; acc1.y += v[j+1].y; acc1.z += v[j+1].z; acc1.w += v[j+1].w;
                acc2.x += v[j+2].x; acc2.y += v[j+2].y; acc2.z += v[j+2].z; acc2.w += v[j+2].w;
                acc3.x += v[j+3].x; acc3.y += v[j+3].y; acc3.z += v[j+3].z; acc3.w += v[j+3].w;
            }
        }

        float4 acc;
        acc.x = (acc0.x + acc1.x) + (acc2.x + acc3.x);
        acc.y = (acc0.y + acc1.y) + (acc2.y + acc3.y);
        acc.z = (acc0.z + acc1.z) + (acc2.z + acc3.z);
        acc.w = (acc0.w + acc1.w) + (acc2.w + acc3.w);

        float4* p = (float4*)(part + ((size_t)b * NCHUNK + chunk) * D);
        p[tid] = acc;
    }
}

// ---------------------------------------------------------------------------
// K2: combine partials -> mean, pre-init enc/out with biases.
// PDL: bias prologue runs while K1 is still executing; part reads wait.
__global__ void combine_kernel(const float* __restrict__ part,
                               float* __restrict__ m,
                               const float* __restrict__ b_enc,
                               float* __restrict__ enc,
                               const float* __restrict__ b_out,
                               float* __restrict__ out) {
    const int i = blockIdx.x * blockDim.x + threadIdx.x;  // 0 .. B*D-1
    const int d = i & (D - 1);

    // Independent prologue (inputs, not touched by K1).
    const float be = b_enc[d];
    const float bo = b_out[d];

    cudaGridDependencySynchronize();   // wait for K1's partials

    const int b = i >> 10;
    float s = 0.f;
    #pragma unroll
    for (int c = 0; c < NCHUNK; c++)
        s += part[((size_t)b * NCHUNK + c) * D + d];
    m[i] = s * (1.0f / (float)S);
    enc[i] = be;
    out[i] = bo;
}

// ---------------------------------------------------------------------------
// K3/K4: split-K batched GEMV with smem-staged activations.
// KSPLIT=4: grid (128, 4) = 512 blocks, KCHUNK=256. Each warp: 2 W float4
// per lane, 2 smem float4 per (b) iteration. Halves block count and atomic
// commits vs KSPLIT=8 while keeping a single wave.
// PDL: W row LDGs (pure input) issue before the dependency sync.
__global__ void __launch_bounds__(256)
gemv_split_kernel(const float* __restrict__ vin,   // [B, D]
                  const float* __restrict__ W,     // [D, D]
                  float* __restrict__ vout) {      // [B, D] (+=)
    __shared__ float4 sh[B * (KCHUNK / 4)];   // 16 x 64 float4 = 16 KB

    const int K0 = blockIdx.y * KCHUNK;
    const int warp = threadIdx.x >> 5;
    const int lane = threadIdx.x & 31;
    const int n = blockIdx.x * 8 + warp;

    // Prologue: W row loads overlap the predecessor's tail + our ramp.
    const float4* Wr = (const float4*)(W + (size_t)n * D + K0);
    const float4 w0 = __ldg(&Wr[lane]);
    const float4 w1 = __ldg(&Wr[lane + 32]);

    cudaGridDependencySynchronize();   // vin/vout now valid

    // Cooperative fill: vin[:, K0:K0+256] -> 16 KB smem. 1024 float4 over
    // 256 threads = 4 per thread: 2 rows (warp, warp+8) x 2 column-halves.
    {
        const float4* v4 = (const float4*)vin;
        #pragma unroll
        for (int r = 0; r < 2; r++) {
            const int row = warp + r * 8;           // 0..15 over b
            sh[row * 64 + lane]      = v4[(size_t)row * (D / 4) + K0 / 4 + lane];
            sh[row * 64 + lane + 32] = v4[(size_t)row * (D / 4) + K0 / 4 + lane + 32];
        }
    }
    __syncthreads();

    float acc[B];
    #pragma unroll
    for (int b = 0; b < B; b++) {
        float4 v0 = sh[b * 64 + lane];
        float4 v1 = sh[b * 64 + lane + 32];
        acc[b] = ((w0.x * v0.x + w0.y * v0.y) + (w0.z * v0.z + w0.w * v0.w))
               + ((w1.x * v1.x + w1.y * v1.y) + (w1.z * v1.z + w1.w * v1.w));
    }

    // Interleaved pairwise reduction: 16 SHFLs; lane l ends with b = l & 15.
    float u8[8];
    #pragma unroll
    for (int j = 0; j < 8; j++) {
        float mine  = (lane & 1) ? acc[2 * j + 1] : acc[2 * j];
        float other = (lane & 1) ? acc[2 * j]     : acc[2 * j + 1];
        u8[j] = mine + __shfl_xor_sync(0xFFFFFFFFu, other, 1);
    }
    float u4[4];
    #pragma unroll
    for (int j = 0; j < 4; j++) {
        float mine  = (lane & 2) ? u8[2 * j + 1] : u8[2 * j];
        float other = (lane & 2) ? u8[2 * j]     : u8[2 * j + 1];
        u4[j] = mine + __shfl_xor_sync(0xFFFFFFFFu, other, 2);
    }
    float u2[2];
    #pragma unroll
    for (int j = 0; j < 2; j++) {
        float mine  = (lane & 4) ? u4[2 * j + 1] : u4[2 * j];
        float other = (lane & 4) ? u4[2 * j]     : u4[2 * j + 1];
        u2[j] = mine + __shfl_xor_sync(0xFFFFFFFFu, other, 4);
    }
    float mine  = (lane & 8) ? u2[1] : u2[0];
    float other = (lane & 8) ? u2[0] : u2[1];
    float u = mine + __shfl_xor_sync(0xFFFFFFFFu, other, 8);
    u += __shfl_xor_sync(0xFFFFFFFFu, u, 16);

    if (lane < B)
        atomicAdd(&vout[(size_t)lane * D + n], u);
}

// ---------------------------------------------------------------------------
extern "C" void kernel_launch(void* const* d_in, const int* in_sizes, int n_in,
                              void* d_out, int out_size) {
    const float* x     = (const float*)d_in[0];
    const float* W_enc = (const float*)d_in[1];
    const float* b_enc = (const float*)d_in[2];
    const float* W_out = (const float*)d_in[3];
    const float* b_out = (const float*)d_in[4];
    float* out = (float*)d_out;

    float* part; cudaGetSymbolAddress((void**)&part, g_part);
    float* m;    cudaGetSymbolAddress((void**)&m,    g_m);
    float* enc;  cudaGetSymbolAddress((void**)&enc,  g_enc);

    // K1: normal launch.
    reduce_partial_kernel<<<R_GRID, 256>>>(x, part);

    // Tail kernels: PDL so each overlaps the predecessor's tail/ramp.
    cudaLaunchAttribute attr[1];
    attr[0].id = cudaLaunchAttributeProgrammaticStreamSerialization;
    attr[0].val.programmaticStreamSerializationAllowed = 1;

    {
        cudaLaunchConfig_t cfg = {};
        cfg.gridDim = dim3((B * D) / 256);
        cfg.blockDim = dim3(256);
        cfg.stream = 0;
        cfg.attrs = attr;
        cfg.numAttrs = 1;
        cudaLaunchKernelEx(&cfg, combine_kernel,
                           (const float*)part, m, b_enc, enc, b_out, out);
    }
    {
        cudaLaunchConfig_t cfg = {};
        cfg.gridDim = dim3(D / 8, KSPLIT);
        cfg.blockDim = dim3(256);
        cfg.stream = 0;
        cfg.attrs = attr;
        cfg.numAttrs = 1;
        cudaLaunchKernelEx(&cfg, gemv_split_kernel,
                           (const float*)m, W_enc, enc);
    }
    {
        cudaLaunchConfig_t cfg = {};
        cfg.gridDim = dim3(D / 8, KSPLIT);
        cfg.blockDim = dim3(256);
        cfg.stream = 0;
        cfg.attrs = attr;
        cfg.numAttrs = 1;
        cudaLaunchKernelEx(&cfg, gemv_split_kernel,
                           (const float*)enc, W_out, out);
    }
}